// round 7
// baseline (speedup 1.0000x reference)
#include <cuda_runtime.h>
#include <cuda_bf16.h>
#include <cstdint>
#include <cstdio>
#include <math.h>

typedef unsigned int u32;

#define Bsz 4
#define Lsz 2048
#define Dsz 512
#define Hsz 8
#define Asz 64
#define Msz (Bsz*Lsz)
#define NKT (Lsz/64)

// ================= scratch =================
__device__ unsigned short g_qcat[(size_t)Bsz*Hsz*Lsz*128];
__device__ unsigned short g_kcat[(size_t)Bsz*Hsz*Lsz*128];
__device__ unsigned short g_v[(size_t)Bsz*Hsz*Lsz*Asz];
__device__ unsigned short g_ctx[(size_t)Bsz*Hsz*Lsz*Asz];
__device__ float g_x[(size_t)Msz*Dsz];

// ================= helpers =================
__device__ __forceinline__ u32 sptr(const void* p)
{
    return (u32)__cvta_generic_to_shared(p);
}

__device__ __forceinline__ void ldmx4(u32* r, const void* p)
{
    asm volatile("ldmatrix.sync.aligned.m8n8.x4.shared.b16 {%0,%1,%2,%3}, [%4];"
                 : "=r"(r[0]), "=r"(r[1]), "=r"(r[2]), "=r"(r[3])
                 : "r"(sptr(p)));
}

__device__ __forceinline__ void ldmx4t(u32* r, const void* p)
{
    asm volatile("ldmatrix.sync.aligned.m8n8.x4.trans.shared.b16 {%0,%1,%2,%3}, [%4];"
                 : "=r"(r[0]), "=r"(r[1]), "=r"(r[2]), "=r"(r[3])
                 : "r"(sptr(p)));
}

__device__ __forceinline__ void mma_bf16(float* d, const u32* a, u32 b0, u32 b1)
{
    asm volatile(
        "mma.sync.aligned.m16n8k16.row.col.f32.bf16.bf16.f32 "
        "{%0,%1,%2,%3}, {%4,%5,%6,%7}, {%8,%9}, {%0,%1,%2,%3};"
        : "+f"(d[0]), "+f"(d[1]), "+f"(d[2]), "+f"(d[3])
        : "r"(a[0]), "r"(a[1]), "r"(a[2]), "r"(a[3]), "r"(b0), "r"(b1));
}

__device__ __forceinline__ u32 pk2(float lo, float hi)
{
    __nv_bfloat162 h = __floats2bfloat162_rn(lo, hi);
    return *reinterpret_cast<u32*>(&h);
}

__device__ __forceinline__ void cpa16(u32 s, const void* g)
{
    asm volatile("cp.async.cg.shared.global [%0], [%1], 16;" :: "r"(s), "l"(g));
}

__device__ __forceinline__ void cpa_commit()
{
    asm volatile("cp.async.commit_group;");
}

// ================= fused projection GEMMs (HMMA, pipelined) =================
struct ProjOne {
    const float* X;
    const float* W;
    const float* Bv;
    __nv_bfloat16* out;
    int CD;
    int coff;
    float scale;
};
struct ProjAll {
    ProjOne p[5];
};

__global__ __launch_bounds__(256) void proj_mma(ProjAll args)
{
    __shared__ __nv_bfloat16 As[128][40];
    __shared__ __nv_bfloat16 Bs[32][136];

    const ProjOne pa = args.p[blockIdx.z];
    const float* __restrict__ X = pa.X;
    const float* __restrict__ W = pa.W;
    const float* __restrict__ bias = pa.Bv;
    __nv_bfloat16* __restrict__ out = pa.out;
    const int CD = pa.CD;
    const int coff = pa.coff;
    const float sc = pa.scale;

    const int tid  = threadIdx.x;
    const int lane = tid & 31;
    const int wid  = tid >> 5;
    const int wm   = wid >> 2;
    const int wn   = wid & 3;
    const int m0   = blockIdx.y * 128;
    const int n0   = blockIdx.x * 128;
    const int lr   = tid >> 3;
    const int lc   = (tid & 7) * 4;
    float acc[4][4][4] = {};

    float4 xa[4];
    float4 wa[4];
    #pragma unroll
    for (int i = 0; i < 4; i++) {
        xa[i] = *(const float4*)(X + (size_t)(m0 + lr + 32*i)*Dsz + lc);
        wa[i] = *(const float4*)(W + (size_t)lr*Dsz + n0 + lc + 32*i);
    }

    for (int k0 = 0; k0 < Dsz; k0 += 32) {
        __syncthreads();
        #pragma unroll
        for (int i = 0; i < 4; i++) {
            uint2 v;
            v.x = pk2(xa[i].x, xa[i].y);
            v.y = pk2(xa[i].z, xa[i].w);
            *(uint2*)(&As[lr + 32*i][lc]) = v;
        }
        #pragma unroll
        for (int i = 0; i < 4; i++) {
            uint2 v;
            v.x = pk2(wa[i].x, wa[i].y);
            v.y = pk2(wa[i].z, wa[i].w);
            *(uint2*)(&Bs[lr][lc + 32*i]) = v;
        }
        __syncthreads();
        if (k0 + 32 < Dsz) {
            #pragma unroll
            for (int i = 0; i < 4; i++) {
                xa[i] = *(const float4*)(X + (size_t)(m0 + lr + 32*i)*Dsz + k0 + 32 + lc);
                wa[i] = *(const float4*)(W + (size_t)(k0 + 32 + lr)*Dsz + n0 + lc + 32*i);
            }
        }
        #pragma unroll
        for (int ks = 0; ks < 32; ks += 16) {
            u32 af[4][4];
            u32 bfr[2][4];
            #pragma unroll
            for (int mt = 0; mt < 4; mt++) {
                ldmx4(af[mt], &As[wm*64 + mt*16 + (lane & 15)][ks + ((lane >> 4) << 3)]);
            }
            #pragma unroll
            for (int g = 0; g < 2; g++) {
                ldmx4t(bfr[g], &Bs[ks + (lane & 15)][wn*32 + g*16 + ((lane >> 4) << 3)]);
            }
            #pragma unroll
            for (int mt = 0; mt < 4; mt++) {
                #pragma unroll
                for (int nt = 0; nt < 4; nt++) {
                    mma_bf16(acc[mt][nt], af[mt],
                             bfr[nt >> 1][(nt & 1)*2], bfr[nt >> 1][(nt & 1)*2 + 1]);
                }
            }
        }
    }

    const int gid = lane >> 2;
    const int tig = lane & 3;
    #pragma unroll
    for (int mt = 0; mt < 4; mt++) {
        #pragma unroll
        for (int nt = 0; nt < 4; nt++) {
            int n = n0 + wn*32 + nt*8 + tig*2;
            float b0 = bias[n];
            float b1 = bias[n + 1];
            int h = n >> 6;
            int a = n & 63;
            #pragma unroll
            for (int rr = 0; rr < 2; rr++) {
                int m  = m0 + wm*64 + mt*16 + gid + rr*8;
                int bb = m >> 11;
                int l  = m & (Lsz - 1);
                __nv_bfloat162 o2 = __floats2bfloat162_rn((acc[mt][nt][rr*2] + b0)*sc,
                                                          (acc[mt][nt][rr*2 + 1] + b1)*sc);
                *reinterpret_cast<__nv_bfloat162*>(
                    out + ((size_t)((bb*Hsz + h)*Lsz) + l)*CD + coff + a) = o2;
            }
        }
    }
}

// ================= output GEMM (HMMA, pipelined) =================
__global__ __launch_bounds__(256) void out_mma(
    const __nv_bfloat16* __restrict__ CTX, const float* __restrict__ W,
    const float* __restrict__ bias, const float* __restrict__ RES,
    float* __restrict__ out)
{
    __shared__ __nv_bfloat16 As[128][40];
    __shared__ __nv_bfloat16 Bs[32][136];

    const int tid  = threadIdx.x;
    const int lane = tid & 31;
    const int wid  = tid >> 5;
    const int wm   = wid >> 2;
    const int wn   = wid & 3;
    const int m0   = blockIdx.y * 128;
    const int n0   = blockIdx.x * 128;
    const int lr   = tid >> 3;
    const int lc   = (tid & 7) * 4;
    float acc[4][4][4] = {};

    uint4 av[2];
    float4 wa[4];
    #pragma unroll
    for (int i = 0; i < 2; i++) {
        int c   = tid + 256*i;
        int row = c >> 2;
        int kc  = (c & 3)*8;
        int m   = m0 + row;
        int bb  = m >> 11;
        int l   = m & (Lsz - 1);
        int h   = kc >> 6;
        int a   = kc & 63;
        av[i] = *(const uint4*)(CTX + ((size_t)((bb*Hsz + h)*Lsz) + l)*Asz + a);
    }
    #pragma unroll
    for (int i = 0; i < 4; i++) {
        wa[i] = *(const float4*)(W + (size_t)lr*Dsz + n0 + lc + 32*i);
    }

    for (int k0 = 0; k0 < Dsz; k0 += 32) {
        __syncthreads();
        #pragma unroll
        for (int i = 0; i < 2; i++) {
            int c   = tid + 256*i;
            int row = c >> 2;
            int kc  = (c & 3)*8;
            *(uint4*)(&As[row][kc]) = av[i];
        }
        #pragma unroll
        for (int i = 0; i < 4; i++) {
            uint2 v;
            v.x = pk2(wa[i].x, wa[i].y);
            v.y = pk2(wa[i].z, wa[i].w);
            *(uint2*)(&Bs[lr][lc + 32*i]) = v;
        }
        __syncthreads();
        if (k0 + 32 < Dsz) {
            #pragma unroll
            for (int i = 0; i < 2; i++) {
                int c   = tid + 256*i;
                int row = c >> 2;
                int kc  = (c & 3)*8;
                int m   = m0 + row;
                int bb  = m >> 11;
                int l   = m & (Lsz - 1);
                int kg  = k0 + 32 + kc;
                int h   = kg >> 6;
                int a   = kg & 63;
                av[i] = *(const uint4*)(CTX + ((size_t)((bb*Hsz + h)*Lsz) + l)*Asz + a);
            }
            #pragma unroll
            for (int i = 0; i < 4; i++) {
                wa[i] = *(const float4*)(W + (size_t)(k0 + 32 + lr)*Dsz + n0 + lc + 32*i);
            }
        }
        #pragma unroll
        for (int ks = 0; ks < 32; ks += 16) {
            u32 af[4][4];
            u32 bfr[2][4];
            #pragma unroll
            for (int mt = 0; mt < 4; mt++) {
                ldmx4(af[mt], &As[wm*64 + mt*16 + (lane & 15)][ks + ((lane >> 4) << 3)]);
            }
            #pragma unroll
            for (int g = 0; g < 2; g++) {
                ldmx4t(bfr[g], &Bs[ks + (lane & 15)][wn*32 + g*16 + ((lane >> 4) << 3)]);
            }
            #pragma unroll
            for (int mt = 0; mt < 4; mt++) {
                #pragma unroll
                for (int nt = 0; nt < 4; nt++) {
                    mma_bf16(acc[mt][nt], af[mt],
                             bfr[nt >> 1][(nt & 1)*2], bfr[nt >> 1][(nt & 1)*2 + 1]);
                }
            }
        }
    }

    const int gid = lane >> 2;
    const int tig = lane & 3;
    #pragma unroll
    for (int mt = 0; mt < 4; mt++) {
        #pragma unroll
        for (int nt = 0; nt < 4; nt++) {
            int n = n0 + wn*32 + nt*8 + tig*2;
            float b0 = bias[n];
            float b1 = bias[n + 1];
            #pragma unroll
            for (int rr = 0; rr < 2; rr++) {
                int m = m0 + wm*64 + mt*16 + gid + rr*8;
                size_t idx = (size_t)m*Dsz + n;
                float2 r2 = *(const float2*)(RES + idx);
                float2 o2;
                o2.x = acc[mt][nt][rr*2] + b0 + r2.x;
                o2.y = acc[mt][nt][rr*2 + 1] + b1 + r2.y;
                *(float2*)(out + idx) = o2;
            }
        }
    }
}

// ================= flash attention (HMMA, S-pipelined across tiles) ==========
// smem: Qs[64][136] | Ks[2][64][136] | Vs[2][64][72]
#define ATTN_SMEM ((64*136 + 2*64*136 + 2*64*72) * 2)

// compute S tile (64x64) for this warp from Qs/Kslot
__device__ __forceinline__ void s_compute(
    const __nv_bfloat16* Qs, const __nv_bfloat16* kcur,
    int lane, int wid, float s[8][4])
{
    #pragma unroll
    for (int nt = 0; nt < 8; nt++) {
        #pragma unroll
        for (int j = 0; j < 4; j++) {
            s[nt][j] = 0.0f;
        }
    }
    #pragma unroll
    for (int ks = 0; ks < 8; ks++) {
        u32 qt[4];
        u32 kb[4][4];
        ldmx4(qt, Qs + (wid*16 + (lane & 15))*136 + ks*16 + ((lane >> 4) << 3));
        #pragma unroll
        for (int g = 0; g < 4; g++) {
            ldmx4(kb[g], kcur + (g*16 + (lane & 15))*136 + ks*16 + ((lane >> 4) << 3));
        }
        #pragma unroll
        for (int nt = 0; nt < 8; nt++) {
            int g   = nt >> 1;
            int odd = nt & 1;
            mma_bf16(s[nt], qt, kb[g][odd], kb[g][odd + 2]);
        }
    }
}

__global__ __launch_bounds__(128) void attn_mma(
    const __nv_bfloat16* __restrict__ QC, const __nv_bfloat16* __restrict__ KC,
    const __nv_bfloat16* __restrict__ V, __nv_bfloat16* __restrict__ CTX)
{
    extern __shared__ __nv_bfloat16 dsm[];
    __nv_bfloat16* Qs = dsm;
    __nv_bfloat16* Ks = dsm + 64*136;
    __nv_bfloat16* Vs = dsm + 64*136 + 2*64*136;

    const int tid  = threadIdx.x;
    const int lane = tid & 31;
    const int wid  = tid >> 5;
    const int gid  = lane >> 2;
    const int tig  = lane & 3;
    const int bh   = blockIdx.y;
    const int q0   = blockIdx.x * 64;

    const __nv_bfloat16* Kbase = KC + (size_t)bh*Lsz*128;
    const __nv_bfloat16* Vbase = V + (size_t)bh*Lsz*64;

    // group 0: K0 -> Kslot0
    #pragma unroll
    for (int i = 0; i < 8; i++) {
        int c  = tid + 128*i;
        int r  = c >> 4;
        int c8 = (c & 15)*8;
        cpa16(sptr(Ks + r*136 + c8), Kbase + (size_t)r*128 + c8);
    }
    cpa_commit();

    // load Q (direct) while K0 is in flight
    const __nv_bfloat16* Qb = QC + ((size_t)bh*Lsz + q0)*128;
    #pragma unroll
    for (int i = 0; i < 8; i++) {
        int c  = tid + 128*i;
        int r  = c >> 4;
        int c8 = (c & 15)*8;
        *(uint4*)(Qs + r*136 + c8) = *(const uint4*)(Qb + (size_t)r*128 + c8);
    }

    asm volatile("cp.async.wait_group 0;");
    __syncthreads();

    float s_prev[8][4];
    float s_nxt[8][4];
    s_compute(Qs, Ks, lane, wid, s_prev);
    __syncthreads();   // all warps done reading K0 before it gets overwritten later

    // group 1: K1 -> Kslot1, V0 -> Vslot0
    #pragma unroll
    for (int i = 0; i < 8; i++) {
        int c  = tid + 128*i;
        int r  = c >> 4;
        int c8 = (c & 15)*8;
        cpa16(sptr(Ks + 64*136 + r*136 + c8), Kbase + (size_t)(64 + r)*128 + c8);
    }
    #pragma unroll
    for (int i = 0; i < 4; i++) {
        int c  = tid + 128*i;
        int r  = c >> 3;
        int c8 = (c & 7)*8;
        cpa16(sptr(Vs + r*72 + c8), Vbase + (size_t)r*64 + c8);
    }
    cpa_commit();

    float o[8][4] = {};
    float mr0 = -1e30f;
    float mr1 = -1e30f;
    float l0 = 0.0f;
    float l1 = 0.0f;

    for (int kt = 0; kt < NKT; kt++) {
        // wait for {K(kt+1), V(kt)} issued last iteration (or prologue)
        asm volatile("cp.async.wait_group 0;");
        __syncthreads();

        // issue S(kt+1) on the tensor pipe (overlaps the softmax below)
        if (kt + 1 < NKT) {
            s_compute(Qs, Ks + ((kt + 1) & 1)*64*136, lane, wid, s_nxt);
        }

        // prefetch K(kt+2) -> Kslot[kt&1], V(kt+1) -> Vslot[(kt+1)&1]
        bool issued = false;
        if (kt + 2 < NKT) {
            const __nv_bfloat16* Kb = Kbase + (size_t)(kt + 2)*64*128;
            __nv_bfloat16* kd = Ks + (kt & 1)*64*136;
            #pragma unroll
            for (int i = 0; i < 8; i++) {
                int c  = tid + 128*i;
                int r  = c >> 4;
                int c8 = (c & 15)*8;
                cpa16(sptr(kd + r*136 + c8), Kb + (size_t)r*128 + c8);
            }
            issued = true;
        }
        if (kt + 1 < NKT) {
            const __nv_bfloat16* Vb = Vbase + (size_t)(kt + 1)*64*64;
            __nv_bfloat16* vd = Vs + ((kt + 1) & 1)*64*72;
            #pragma unroll
            for (int i = 0; i < 4; i++) {
                int c  = tid + 128*i;
                int r  = c >> 3;
                int c8 = (c & 7)*8;
                cpa16(sptr(vd + r*72 + c8), Vb + (size_t)r*64 + c8);
            }
            issued = true;
        }
        if (issued) {
            cpa_commit();
        }

        // softmax on s_prev (exp2 domain; Q was prescaled by 0.125*log2(e))
        float mx0 = -1e30f;
        float mx1 = -1e30f;
        #pragma unroll
        for (int nt = 0; nt < 8; nt++) {
            mx0 = fmaxf(mx0, fmaxf(s_prev[nt][0], s_prev[nt][1]));
            mx1 = fmaxf(mx1, fmaxf(s_prev[nt][2], s_prev[nt][3]));
        }
        mx0 = fmaxf(mx0, __shfl_xor_sync(0xffffffffu, mx0, 1));
        mx0 = fmaxf(mx0, __shfl_xor_sync(0xffffffffu, mx0, 2));
        mx1 = fmaxf(mx1, __shfl_xor_sync(0xffffffffu, mx1, 1));
        mx1 = fmaxf(mx1, __shfl_xor_sync(0xffffffffu, mx1, 2));

        float mn0 = fmaxf(mr0, mx0);
        float mn1 = fmaxf(mr1, mx1);
        float cf0 = exp2f(mr0 - mn0);
        float cf1 = exp2f(mr1 - mn1);
        float sm0 = 0.0f;
        float sm1 = 0.0f;
        #pragma unroll
        for (int nt = 0; nt < 8; nt++) {
            s_prev[nt][0] = exp2f(s_prev[nt][0] - mn0);
            s_prev[nt][1] = exp2f(s_prev[nt][1] - mn0);
            s_prev[nt][2] = exp2f(s_prev[nt][2] - mn1);
            s_prev[nt][3] = exp2f(s_prev[nt][3] - mn1);
            sm0 += s_prev[nt][0] + s_prev[nt][1];
            sm1 += s_prev[nt][2] + s_prev[nt][3];
        }
        sm0 += __shfl_xor_sync(0xffffffffu, sm0, 1);
        sm0 += __shfl_xor_sync(0xffffffffu, sm0, 2);
        sm1 += __shfl_xor_sync(0xffffffffu, sm1, 1);
        sm1 += __shfl_xor_sync(0xffffffffu, sm1, 2);
        l0 = l0*cf0 + sm0;
        l1 = l1*cf1 + sm1;
        mr0 = mn0;
        mr1 = mn1;
        #pragma unroll
        for (int nt = 0; nt < 8; nt++) {
            o[nt][0] *= cf0;
            o[nt][1] *= cf0;
            o[nt][2] *= cf1;
            o[nt][3] *= cf1;
        }

        // PV on tile kt
        const __nv_bfloat16* vc = Vs + (kt & 1)*64*72;
        #pragma unroll
        for (int j = 0; j < 4; j++) {
            u32 pf[4];
            u32 vb[4][4];
            pf[0] = pk2(s_prev[2*j][0], s_prev[2*j][1]);
            pf[1] = pk2(s_prev[2*j][2], s_prev[2*j][3]);
            pf[2] = pk2(s_prev[2*j + 1][0], s_prev[2*j + 1][1]);
            pf[3] = pk2(s_prev[2*j + 1][2], s_prev[2*j + 1][3]);
            #pragma unroll
            for (int g = 0; g < 4; g++) {
                ldmx4t(vb[g], vc + (j*16 + (lane & 15))*72 + g*16 + ((lane >> 4) << 3));
            }
            #pragma unroll
            for (int nt = 0; nt < 8; nt++) {
                int g   = nt >> 1;
                int odd = (nt & 1)*2;
                mma_bf16(o[nt], pf, vb[g][odd], vb[g][odd + 1]);
            }
        }

        if (kt + 1 < NKT) {
            #pragma unroll
            for (int nt = 0; nt < 8; nt++) {
                #pragma unroll
                for (int j = 0; j < 4; j++) {
                    s_prev[nt][j] = s_nxt[nt][j];
                }
            }
        }
    }

    float iv0 = 1.0f / l0;
    float iv1 = 1.0f / l1;
    int r0 = q0 + wid*16 + gid;
    #pragma unroll
    for (int nt = 0; nt < 8; nt++) {
        int cn = nt*8 + tig*2;
        *reinterpret_cast<__nv_bfloat162*>(CTX + ((size_t)bh*Lsz + r0)*Asz + cn) =
            __floats2bfloat162_rn(o[nt][0]*iv0, o[nt][1]*iv0);
        *reinterpret_cast<__nv_bfloat162*>(CTX + ((size_t)bh*Lsz + r0 + 8)*Asz + cn) =
            __floats2bfloat162_rn(o[nt][2]*iv1, o[nt][3]*iv1);
    }
}

// ================= LayerNorm (2 rows/block, float4) =================
__global__ __launch_bounds__(256) void ln_kernel(
    const float* __restrict__ X, const float* __restrict__ g,
    const float* __restrict__ b, float* __restrict__ out)
{
    const int tid = threadIdx.x;
    const int rsel = tid >> 7;          // 0 or 1
    const int sub = tid & 127;          // 0..127
    const int row = blockIdx.x*2 + rsel;

    float4 v = *(const float4*)(X + (size_t)row*Dsz + sub*4);
    float s1 = v.x + v.y + v.z + v.w;
    float s2 = v.x*v.x + v.y*v.y + v.z*v.z + v.w*v.w;
    #pragma unroll
    for (int off = 16; off; off >>= 1) {
        s1 += __shfl_xor_sync(0xffffffffu, s1, off);
        s2 += __shfl_xor_sync(0xffffffffu, s2, off);
    }
    __shared__ float ws[2][4];
    __shared__ float w2[2][4];
    __shared__ float mu_s[2];
    __shared__ float rs_s[2];
    int w = (tid >> 5) & 3;
    if ((tid & 31) == 0) {
        ws[rsel][w] = s1;
        w2[rsel][w] = s2;
    }
    __syncthreads();
    if (sub == 0) {
        float S = ws[rsel][0] + ws[rsel][1] + ws[rsel][2] + ws[rsel][3];
        float S2 = w2[rsel][0] + w2[rsel][1] + w2[rsel][2] + w2[rsel][3];
        float mu = S*(1.0f/Dsz);
        float var = S2*(1.0f/Dsz) - mu*mu;
        mu_s[rsel] = mu;
        rs_s[rsel] = rsqrtf(var + 1e-5f);
    }
    __syncthreads();
    float mu = mu_s[rsel];
    float rs = rs_s[rsel];
    float4 gg = *(const float4*)(g + sub*4);
    float4 bb = *(const float4*)(b + sub*4);
    float4 ov;
    ov.x = (v.x - mu)*rs*gg.x + bb.x;
    ov.y = (v.y - mu)*rs*gg.y + bb.y;
    ov.z = (v.z - mu)*rs*gg.z + bb.z;
    ov.w = (v.w - mu)*rs*gg.w + bb.w;
    *(float4*)(out + (size_t)row*Dsz + sub*4) = ov;
}

// ================= launcher =================
extern "C" void kernel_launch(void* const* d_in, const int* in_sizes, int n_in,
                              void* d_out, int out_size)
{
    const float* Qd = (const float*)d_in[0];
    const float* Qt = (const float*)d_in[1];
    const float* Kd = (const float*)d_in[2];
    const float* Kt = (const float*)d_in[3];
    const float* Vt = (const float*)d_in[4];
    const float* Wqd;
    const float* Wqt;
    const float* Wkd;
    const float* Wkt;
    const float* Wvt;
    const float* Wo;
    const float* bqd;
    const float* bqt;
    const float* bkd;
    const float* bkt;
    const float* bvt;
    const float* bo;
    if (in_sizes[6] == Dsz) {
        Wqd = (const float*)d_in[5];
        bqd = (const float*)d_in[6];
        Wqt = (const float*)d_in[7];
        bqt = (const float*)d_in[8];
        Wkd = (const float*)d_in[9];
        bkd = (const float*)d_in[10];
        Wkt = (const float*)d_in[11];
        bkt = (const float*)d_in[12];
        Wvt = (const float*)d_in[13];
        bvt = (const float*)d_in[14];
        Wo  = (const float*)d_in[15];
        bo  = (const float*)d_in[16];
    } else {
        Wqd = (const float*)d_in[5];
        Wqt = (const float*)d_in[6];
        Wkd = (const float*)d_in[7];
        Wkt = (const float*)d_in[8];
        Wvt = (const float*)d_in[9];
        Wo  = (const float*)d_in[10];
        bqd = (const float*)d_in[11];
        bqt = (const float*)d_in[12];
        bkd = (const float*)d_in[13];
        bkt = (const float*)d_in[14];
        bvt = (const float*)d_in[15];
        bo  = (const float*)d_in[16];
    }
    const float* lg = (const float*)d_in[17];
    const float* lb = (const float*)d_in[18];

    void* p_qcat = 0;
    void* p_kcat = 0;
    void* p_v = 0;
    void* p_ctx = 0;
    void* p_x = 0;
    cudaGetSymbolAddress(&p_qcat, g_qcat);
    cudaGetSymbolAddress(&p_kcat, g_kcat);
    cudaGetSymbolAddress(&p_v, g_v);
    cudaGetSymbolAddress(&p_ctx, g_ctx);
    cudaGetSymbolAddress(&p_x, g_x);
    __nv_bfloat16* qcat = (__nv_bfloat16*)p_qcat;
    __nv_bfloat16* kcat = (__nv_bfloat16*)p_kcat;
    __nv_bfloat16* vv   = (__nv_bfloat16*)p_v;
    __nv_bfloat16* ctx  = (__nv_bfloat16*)p_ctx;
    float* xx = (float*)p_x;

    static int smem_set = 0;
    if (!smem_set) {
        cudaFuncSetAttribute(attn_mma,
                             cudaFuncAttributeMaxDynamicSharedMemorySize, ATTN_SMEM);
        smem_set = 1;
    }

    const float QSC = 0.125f * 1.4426950408889634f;   // fold 1/sqrt(64) * log2(e)
    ProjAll pj;
    pj.p[0].X = Qd;  pj.p[0].W = Wqd; pj.p[0].Bv = bqd; pj.p[0].out = qcat; pj.p[0].CD = 128; pj.p[0].coff = 0;  pj.p[0].scale = QSC;
    pj.p[1].X = Qt;  pj.p[1].W = Wqt; pj.p[1].Bv = bqt; pj.p[1].out = qcat; pj.p[1].CD = 128; pj.p[1].coff = 64; pj.p[1].scale = QSC;
    pj.p[2].X = Kd;  pj.p[2].W = Wkd; pj.p[2].Bv = bkd; pj.p[2].out = kcat; pj.p[2].CD = 128; pj.p[2].coff = 0;  pj.p[2].scale = 1.0f;
    pj.p[3].X = Kt;  pj.p[3].W = Wkt; pj.p[3].Bv = bkt; pj.p[3].out = kcat; pj.p[3].CD = 128; pj.p[3].coff = 64; pj.p[3].scale = 1.0f;
    pj.p[4].X = Vt;  pj.p[4].W = Wvt; pj.p[4].Bv = bvt; pj.p[4].out = vv;   pj.p[4].CD = 64;  pj.p[4].coff = 0;  pj.p[4].scale = 1.0f;

    dim3 gp(Dsz/128, Msz/128, 5);
    dim3 go(Dsz/128, Msz/128);
    dim3 ga(Lsz/64, Bsz*Hsz);
    proj_mma<<<gp, 256>>>(pj);
    attn_mma<<<ga, 128, ATTN_SMEM>>>(qcat, kcat, vv, ctx);
    out_mma<<<go, 256>>>(ctx, Wo, bo, Qd, xx);
    ln_kernel<<<Msz/2, 256>>>(xx, lg, lb, (float*)d_out);
}